// round 12
// baseline (speedup 1.0000x reference)
#include <cuda_runtime.h>
#include <cuda_fp16.h>
#include <stdint.h>
#include <math.h>

// Problem dims
#define S_TOT 4096     // BS*N
#define D_DIM 1024
#define T_DIM 2048
#define V_DIM 32000
#define NB 8

// Scratch (device globals — allocation-free rule)
__device__ float g_x[S_TOT * D_DIM];
__device__ float g_xb[S_TOT * T_DIM];
__device__ float g_zhat[S_TOT * NB * 64];
__device__ float g_pcm[2 * S_TOT * NB];
__device__ __half g_Ah[(size_t)S_TOT * 1024];    // logits A plain fp16
__device__ __half g_Bh[(size_t)V_DIM * 1024];    // emb fp16
__device__ __half g_Axo[(size_t)S_TOT * 2048];   // fan_out A 2-term (hi|lo)
__device__ __half g_Bfo[(size_t)T_DIM * 1024];   // fo_w^T plain fp16
__device__ __half g_Axi[(size_t)S_TOT * 4096];   // fan_in A 2-term
__device__ __half g_Bfi[(size_t)D_DIM * 2048];   // fi_w^T plain fp16
__device__ __half g_W1p[NB * 256 * 64];
__device__ __half g_W2p[NB * 64 * 256];

__device__ __forceinline__ uint32_t smem_u32(const void* p) {
    uint32_t a;
    asm("{ .reg .u64 t; cvta.to.shared.u64 t, %1; cvt.u32.u64 %0, t; }"
        : "=r"(a) : "l"(p));
    return a;
}
__device__ __forceinline__ void ldsm4(uint32_t* r, uint32_t addr) {
    asm volatile("ldmatrix.sync.aligned.m8n8.x4.shared.b16 {%0,%1,%2,%3}, [%4];"
                 : "=r"(r[0]), "=r"(r[1]), "=r"(r[2]), "=r"(r[3]) : "r"(addr));
}
__device__ __forceinline__ void mma16816(float* c, const uint32_t* a,
                                         uint32_t b0, uint32_t b1) {
    asm volatile(
        "mma.sync.aligned.m16n8k16.row.col.f32.f16.f16.f32 "
        "{%0,%1,%2,%3}, {%4,%5,%6,%7}, {%8,%9}, {%0,%1,%2,%3};"
        : "+f"(c[0]), "+f"(c[1]), "+f"(c[2]), "+f"(c[3])
        : "r"(a[0]), "r"(a[1]), "r"(a[2]), "r"(a[3]), "r"(b0), "r"(b1));
}
__device__ __forceinline__ float gelu_f(float v) {
    float u = 0.7978845608028654f * (v + 0.044715f * v * v * v);
    float th;
    asm("tanh.approx.f32 %0, %1;" : "=f"(th) : "f"(u));
    return 0.5f * v * (1.0f + th);
}
__device__ __forceinline__ uint32_t pack_h2(float a, float b) {
    __half ha = __float2half_rn(a), hb = __float2half_rn(b);
    return (uint32_t)__half_as_ushort(ha) | ((uint32_t)__half_as_ushort(hb) << 16);
}

// ---------------------------------------------------------------------------
// Conversions
// ---------------------------------------------------------------------------
__global__ void conv_h(const float* __restrict__ src, __half* __restrict__ dst) {
    size_t i = (size_t)blockIdx.x * 256 + threadIdx.x;
    float4 v = ((const float4*)src)[i];
    uint2 H;
    H.x = pack_h2(v.x, v.y); H.y = pack_h2(v.z, v.w);
    ((uint2*)dst)[i] = H;
}

__global__ void convA2(const float* __restrict__ src, __half* __restrict__ dst,
                       int K) {
    int row = blockIdx.x;
    const float4* sp = (const float4*)(src + (size_t)row * K);
    __half* base = dst + (size_t)row * 2 * K;
    for (int q = threadIdx.x; q < K / 4; q += 256) {
        float4 v = sp[q];
        __half h0 = __float2half_rn(v.x), h1 = __float2half_rn(v.y);
        __half h2 = __float2half_rn(v.z), h3 = __float2half_rn(v.w);
        uint2 H, L;
        H.x = pack_h2(v.x, v.y); H.y = pack_h2(v.z, v.w);
        L.x = pack_h2(v.x - __half2float(h0), v.y - __half2float(h1));
        L.y = pack_h2(v.z - __half2float(h2), v.w - __half2float(h3));
        *(uint2*)(base + q * 4)     = H;
        *(uint2*)(base + K + q * 4) = L;
    }
}

__global__ void convBT(const float* __restrict__ src, __half* __restrict__ dst,
                       int K, int N) {
    __shared__ float tile[32][33];
    int k0 = blockIdx.x * 32, n0 = blockIdx.y * 32;
    int tx = threadIdx.x & 31, ty = threadIdx.x >> 5;
    for (int i = ty; i < 32; i += 8)
        tile[i][tx] = src[(size_t)(k0 + i) * N + n0 + tx];
    __syncthreads();
    for (int i = ty; i < 32; i += 8) {
        int n = n0 + i;
        dst[(size_t)n * K + k0 + tx] = __float2half_rn(tile[tx][i]);
    }
}

__global__ void convW1p(const float* __restrict__ W1, __half* __restrict__ W1p) {
    int idx = blockIdx.x * 256 + threadIdx.x;
    int t = idx >> 14, rem = idx & 16383;
    int rr = rem >> 6, ph = (rem >> 3) & 7, j = rem & 7;
    int k = ((ph ^ (rr & 7)) << 3) | j;
    W1p[idx] = __float2half_rn(W1[((size_t)t * 64 + k) * 256 + rr]);
}
__global__ void convW2p(const float* __restrict__ W2, __half* __restrict__ W2p) {
    int idx = blockIdx.x * 256 + threadIdx.x;
    int t = idx >> 14, rem = idx & 16383;
    int rr = rem >> 8, ph = (rem >> 3) & 31, j = rem & 7;
    int c = (ph & ~7) | ((ph & 7) ^ (rr & 7));
    int k = (c << 3) | j;
    W2p[idx] = __float2half_rn(W2[((size_t)t * 256 + k) * 64 + rr]);
}

// ---------------------------------------------------------------------------
// Embedding gather + pos add, fused with fan_out A 2-term split (hi|lo)
// ---------------------------------------------------------------------------
__global__ void embed_split(const int* __restrict__ ids,
                            const float* __restrict__ emb,
                            const float* __restrict__ pos,
                            __half* __restrict__ Axo) {
    int s = blockIdx.x;
    int q = threadIdx.x;
    int id = ids[s];
    float4 e = ((const float4*)(emb + (size_t)id * D_DIM))[q];
    float4 p = ((const float4*)(pos + (size_t)(s & 1023) * D_DIM))[q];
    float vx = e.x + p.x, vy = e.y + p.y, vz = e.z + p.z, vw = e.w + p.w;
    __half h0 = __float2half_rn(vx), h1 = __float2half_rn(vy);
    __half h2 = __float2half_rn(vz), h3 = __float2half_rn(vw);
    uint2 H, L;
    H.x = pack_h2(vx, vy); H.y = pack_h2(vz, vw);
    L.x = pack_h2(vx - __half2float(h0), vy - __half2float(h1));
    L.y = pack_h2(vz - __half2float(h2), vw - __half2float(h3));
    __half* base = Axo + (size_t)s * 2048 + q * 4;
    *(uint2*)base = H;
    *(uint2*)(base + 1024) = L;
}

// ---------------------------------------------------------------------------
// HMMA fp16 GEMM, 128x128 tile, 3-stage pipeline (fan_out / fan_in)
// ---------------------------------------------------------------------------
#define HBUF 32768
#define HSMEM (3 * HBUF)

__global__ __launch_bounds__(256) void gemm_hmma(
    const __half* __restrict__ A, const __half* __restrict__ B,
    const float* __restrict__ bias, float* __restrict__ C,
    int ldA, int ldB, int N, int nch, int bkmask) {
    extern __shared__ __align__(128) char smem[];
    const uint32_t sb = smem_u32(smem);
    const int tid = threadIdx.x, lane = tid & 31, wid = tid >> 5;
    const int bm = blockIdx.x * 128, bn = blockIdx.y * 128;
    const int wm = (wid & 1) * 64, wn = (wid >> 1) * 32;

    float acc[4][4][4] = {};

    auto issue = [&](int ch, int buf) {
        int k0 = ch * 64;
        int bk = k0 & bkmask;
        uint32_t abase = sb + buf * HBUF;
        uint32_t bbase = abase + 16384;
#pragma unroll
        for (int i = 0; i < 4; i++) {
            int idx = tid + 256 * i;
            int r = idx >> 3, c = idx & 7;
            uint32_t off = (uint32_t)(r * 128 + ((c ^ (r & 7)) * 16));
            const __half* gp = A + (size_t)(bm + r) * ldA + k0 + c * 8;
            asm volatile("cp.async.cg.shared.global [%0], [%1], 16;"
                         :: "r"(abase + off), "l"(gp));
        }
#pragma unroll
        for (int i = 0; i < 4; i++) {
            int idx = tid + 256 * i;
            int r = idx >> 3, c = idx & 7;
            uint32_t off = (uint32_t)(r * 128 + ((c ^ (r & 7)) * 16));
            const __half* gp = B + (size_t)(bn + r) * ldB + bk + c * 8;
            asm volatile("cp.async.cg.shared.global [%0], [%1], 16;"
                         :: "r"(bbase + off), "l"(gp));
        }
        asm volatile("cp.async.commit_group;" ::: "memory");
    };

    issue(0, 0);
    issue(1, 1);

    int buf = 0;
    for (int ch = 0; ch < nch; ch++) {
        if (ch + 1 < nch) {
            asm volatile("cp.async.wait_group 1;" ::: "memory");
        } else {
            asm volatile("cp.async.wait_group 0;" ::: "memory");
        }
        __syncthreads();
        if (ch + 2 < nch) {
            int nb = buf + 2;
            if (nb >= 3) nb -= 3;
            issue(ch + 2, nb);
        }

        uint32_t abase = sb + buf * HBUF;
        uint32_t bbase = abase + 16384;
#pragma unroll
        for (int ks = 0; ks < 4; ks++) {
            uint32_t afr[4][4];
#pragma unroll
            for (int mi = 0; mi < 4; mi++) {
                int r = wm + mi * 16 + (lane & 15);
                int cu = ks * 2 + (lane >> 4);
                uint32_t addr = abase + r * 128 + ((cu ^ (r & 7)) * 16);
                ldsm4(afr[mi], addr);
            }
            uint32_t bfr[2][4];
#pragma unroll
            for (int p = 0; p < 2; p++) {
                int r = wn + p * 16 + (lane & 7) + ((lane >> 4) * 8);
                int cu = ks * 2 + ((lane >> 3) & 1);
                uint32_t addr = bbase + r * 128 + ((cu ^ (r & 7)) * 16);
                ldsm4(bfr[p], addr);
            }
#pragma unroll
            for (int mi = 0; mi < 4; mi++)
#pragma unroll
                for (int nj = 0; nj < 4; nj++)
                    mma16816(acc[mi][nj], afr[mi],
                             bfr[nj >> 1][(nj & 1) * 2 + 0],
                             bfr[nj >> 1][(nj & 1) * 2 + 1]);
        }
        if (++buf == 3) buf = 0;
    }

#pragma unroll
    for (int mi = 0; mi < 4; mi++) {
#pragma unroll
        for (int nj = 0; nj < 4; nj++) {
            int row = bm + wm + mi * 16 + (lane >> 2);
            int col = bn + wn + nj * 8 + (lane & 3) * 2;
            float b0 = bias ? bias[col] : 0.0f;
            float b1 = bias ? bias[col + 1] : 0.0f;
            float2 v0 = make_float2(acc[mi][nj][0] + b0, acc[mi][nj][1] + b1);
            float2 v1 = make_float2(acc[mi][nj][2] + b0, acc[mi][nj][3] + b1);
            *(float2*)(C + (size_t)row * N + col) = v0;
            *(float2*)(C + (size_t)(row + 8) * N + col) = v1;
        }
    }
}

// ---------------------------------------------------------------------------
// HMMA fp16 GEMM, 256x128 tile, 512 threads, 3-stage pipeline (logits).
// Halves B L2 traffic vs 128x128. Warp tile 64x32 (same reg structure).
// Per buffer: A 256x64 fp16 = 32KB, B 128x64 = 16KB -> 48KB; 3 bufs = 144KB.
// ---------------------------------------------------------------------------
#define M256BUF 49152
#define M256_SMEM (3 * M256BUF)
__global__ __launch_bounds__(512) void gemm_hmma_m256(
    const __half* __restrict__ A, const __half* __restrict__ B,
    float* __restrict__ C, int ldA, int ldB, int N, int nch) {
    extern __shared__ __align__(128) char smem[];
    const uint32_t sb = smem_u32(smem);
    const int tid = threadIdx.x, lane = tid & 31, wid = tid >> 5;
    const int bm = blockIdx.x * 256, bn = blockIdx.y * 128;
    const int wm = (wid & 3) * 64, wn = (wid >> 2) * 32;

    float acc[4][4][4] = {};

    auto issue = [&](int ch, int buf) {
        int k0 = ch * 64;
        uint32_t abase = sb + buf * M256BUF;
        uint32_t bbase = abase + 32768;
#pragma unroll
        for (int i = 0; i < 4; i++) {        // A: 2048 16B units / 512 thr
            int idx = tid + 512 * i;
            int r = idx >> 3, c = idx & 7;
            uint32_t off = (uint32_t)(r * 128 + ((c ^ (r & 7)) * 16));
            const __half* gp = A + (size_t)(bm + r) * ldA + k0 + c * 8;
            asm volatile("cp.async.cg.shared.global [%0], [%1], 16;"
                         :: "r"(abase + off), "l"(gp));
        }
#pragma unroll
        for (int i = 0; i < 2; i++) {        // B: 1024 16B units / 512 thr
            int idx = tid + 512 * i;
            int r = idx >> 3, c = idx & 7;
            uint32_t off = (uint32_t)(r * 128 + ((c ^ (r & 7)) * 16));
            const __half* gp = B + (size_t)(bn + r) * ldB + k0 + c * 8;
            asm volatile("cp.async.cg.shared.global [%0], [%1], 16;"
                         :: "r"(bbase + off), "l"(gp));
        }
        asm volatile("cp.async.commit_group;" ::: "memory");
    };

    issue(0, 0);
    issue(1, 1);

    int buf = 0;
    for (int ch = 0; ch < nch; ch++) {
        if (ch + 1 < nch) {
            asm volatile("cp.async.wait_group 1;" ::: "memory");
        } else {
            asm volatile("cp.async.wait_group 0;" ::: "memory");
        }
        __syncthreads();
        if (ch + 2 < nch) {
            int nb = buf + 2;
            if (nb >= 3) nb -= 3;
            issue(ch + 2, nb);
        }

        uint32_t abase = sb + buf * M256BUF;
        uint32_t bbase = abase + 32768;
#pragma unroll
        for (int ks = 0; ks < 4; ks++) {
            uint32_t afr[4][4];
#pragma unroll
            for (int mi = 0; mi < 4; mi++) {
                int r = wm + mi * 16 + (lane & 15);
                int cu = ks * 2 + (lane >> 4);
                uint32_t addr = abase + r * 128 + ((cu ^ (r & 7)) * 16);
                ldsm4(afr[mi], addr);
            }
            uint32_t bfr[2][4];
#pragma unroll
            for (int p = 0; p < 2; p++) {
                int r = wn + p * 16 + (lane & 7) + ((lane >> 4) * 8);
                int cu = ks * 2 + ((lane >> 3) & 1);
                uint32_t addr = bbase + r * 128 + ((cu ^ (r & 7)) * 16);
                ldsm4(bfr[p], addr);
            }
#pragma unroll
            for (int mi = 0; mi < 4; mi++)
#pragma unroll
                for (int nj = 0; nj < 4; nj++)
                    mma16816(acc[mi][nj], afr[mi],
                             bfr[nj >> 1][(nj & 1) * 2 + 0],
                             bfr[nj >> 1][(nj & 1) * 2 + 1]);
        }
        if (++buf == 3) buf = 0;
    }

#pragma unroll
    for (int mi = 0; mi < 4; mi++) {
#pragma unroll
        for (int nj = 0; nj < 4; nj++) {
            int row = bm + wm + mi * 16 + (lane >> 2);
            int col = bn + wn + nj * 8 + (lane & 3) * 2;
            float2 v0 = make_float2(acc[mi][nj][0], acc[mi][nj][1]);
            float2 v1 = make_float2(acc[mi][nj][2], acc[mi][nj][3]);
            *(float2*)(C + (size_t)row * N + col) = v0;
            *(float2*)(C + (size_t)(row + 8) * N + col) = v1;
        }
    }
}

// ---------------------------------------------------------------------------
// Fused HMMA refine MLP + z-pass. Phase2 uses PLAIN fp16 H (K'=256).
// ---------------------------------------------------------------------------
#define MLPTC_SMEM (122880)
__global__ __launch_bounds__(256) void mlp_tc(
    float* __restrict__ xb, const __half* __restrict__ W1p,
    const __half* __restrict__ W2p, const float* __restrict__ Wz,
    float* __restrict__ zhat, float* __restrict__ pcm,
    const float* __restrict__ lam_logit, int r) {
    extern __shared__ __align__(128) char smem[];
    const uint32_t sb = smem_u32(smem);
    const uint32_t XS = sb, W1S = sb + 32768, HS = sb, W2S = sb + 65536;
    const uint32_t WZS = sb + 98304;
    float* wzsp = (float*)(smem + 98304);
    float* zsp = (float*)(smem + 114688);
    const int tid = threadIdx.x, lane = tid & 31, wid = tid >> 5;
    const int t = blockIdx.y, rt = blockIdx.x;
    const int wm = (wid & 1) * 64;
    float lam = 1.0f;
    if (r > 0) lam = 1.0f / (1.0f + expf(-lam_logit[0]));

    {
        const __half* w1g = W1p + (size_t)t * 16384;
        const __half* w2g = W2p + (size_t)t * 16384;
        const float* wzg = Wz + (size_t)t * 4096;
#pragma unroll
        for (int i = 0; i < 8; i++) {
            int idx = tid + 256 * i;
            asm volatile("cp.async.cg.shared.global [%0], [%1], 16;"
                         :: "r"(W1S + idx * 16), "l"(w1g + idx * 8));
        }
#pragma unroll
        for (int i = 0; i < 8; i++) {
            int idx = tid + 256 * i;
            asm volatile("cp.async.cg.shared.global [%0], [%1], 16;"
                         :: "r"(W2S + idx * 16), "l"(w2g + idx * 8));
        }
#pragma unroll
        for (int i = 0; i < 4; i++) {
            int idx = tid + 256 * i;
            asm volatile("cp.async.cg.shared.global [%0], [%1], 16;"
                         :: "r"(WZS + idx * 16), "l"(wzg + idx * 4));
        }
        asm volatile("cp.async.commit_group;" ::: "memory");
    }

#pragma unroll
    for (int i = 0; i < 4; i++) {
        int idx = tid + 256 * i;
        int lr = idx >> 3, c = idx & 7;
        int g = rt * 128 + lr;
        const float* xp = xb + ((size_t)(g >> 2) * 32 + t * 4 + (g & 3)) * 64 + c * 8;
        float4 v0 = *(const float4*)xp;
        float4 v1 = *(const float4*)(xp + 4);
        float vv[8] = {v0.x, v0.y, v0.z, v0.w, v1.x, v1.y, v1.z, v1.w};
        uint4 Hh, Ll;
        uint32_t* hw = (uint32_t*)&Hh;
        uint32_t* lw = (uint32_t*)&Ll;
#pragma unroll
        for (int j = 0; j < 4; j++) {
            float a = vv[2 * j], b = vv[2 * j + 1];
            __half ha = __float2half_rn(a), hb = __float2half_rn(b);
            hw[j] = (uint32_t)__half_as_ushort(ha) |
                    ((uint32_t)__half_as_ushort(hb) << 16);
            lw[j] = pack_h2(a - __half2float(ha), b - __half2float(hb));
        }
        int phh = c ^ (lr & 7);
        *(uint4*)(smem + lr * 256 + phh * 16) = Hh;
        *(uint4*)(smem + lr * 256 + (8 + phh) * 16) = Ll;
    }
    __syncthreads();

    {
        int s_loc = tid >> 3;
        int d0 = (tid & 7) * 8;
        float zv[8] = {};
#pragma unroll
        for (int c = 0; c < 4; c++) {
            int lr = s_loc * 4 + c;
            int byte_off = lr * 256 + (((d0 >> 3) ^ (lr & 7)) * 16);
            uint4 hi = *(const uint4*)(smem + byte_off);
            uint4 lo = *(const uint4*)(smem + byte_off + 128);
            const __half2* hp = (const __half2*)&hi;
            const __half2* lp = (const __half2*)&lo;
#pragma unroll
            for (int j = 0; j < 4; j++) {
                float2 h2 = __half22float2(hp[j]);
                float2 l2 = __half22float2(lp[j]);
                zv[2 * j]     += h2.x + l2.x;
                zv[2 * j + 1] += h2.y + l2.y;
            }
        }
#pragma unroll
        for (int j = 0; j < 8; j++) zsp[s_loc * 64 + d0 + j] = 0.25f * zv[j];
    }
    asm volatile("cp.async.wait_group 0;" ::: "memory");
    __syncthreads();

    {
        int s_loc = tid >> 3, e0 = (tid & 7) * 8;
        int st = (rt * 32 + s_loc) * 8 + t;
        const float* zr = zsp + s_loc * 64;
        float acc[8] = {};
        for (int d = 0; d < 64; d++) {
            float zv = zr[d];
            const float* wr = wzsp + d * 64 + e0;
#pragma unroll
            for (int j = 0; j < 8; j++) acc[j] = fmaf(zv, wr[j], acc[j]);
        }
        if (r > 0) {
            float sq = 0.0f;
#pragma unroll
            for (int j = 0; j < 8; j++) {
                float diff = zhat[(size_t)st * 64 + e0 + j] - zr[e0 + j];
                sq = fmaf(diff, diff, sq);
            }
            sq += __shfl_down_sync(0xffffffffu, sq, 4, 8);
            sq += __shfl_down_sync(0xffffffffu, sq, 2, 8);
            sq += __shfl_down_sync(0xffffffffu, sq, 1, 8);
            if ((tid & 7) == 0)
                pcm[(size_t)(r - 1) * (S_TOT * NB) + st] = sq;
        }
#pragma unroll
        for (int j = 0; j < 8; j++) zhat[(size_t)st * 64 + e0 + j] = acc[j];
    }

    float acc1[4][8][4] = {};
    {
        const int wn1 = (wid >> 1) * 64;
#pragma unroll
        for (int ks = 0; ks < 8; ks++) {
            uint32_t afr[4][4];
#pragma unroll
            for (int mi = 0; mi < 4; mi++) {
                int rr = wm + mi * 16 + (lane & 15);
                int cu = ks * 2 + (lane >> 4);
                int ph = (cu & 8) | ((cu & 7) ^ (rr & 7));
                ldsm4(afr[mi], XS + rr * 256 + ph * 16);
            }
            uint32_t bfr[4][4];
#pragma unroll
            for (int p = 0; p < 4; p++) {
                int rr = wn1 + p * 16 + (lane & 7) + ((lane >> 4) * 8);
                int cu = (ks * 2 + ((lane >> 3) & 1)) & 7;
                int ph = cu ^ (rr & 7);
                ldsm4(bfr[p], W1S + rr * 128 + ph * 16);
            }
#pragma unroll
            for (int mi = 0; mi < 4; mi++)
#pragma unroll
                for (int nj = 0; nj < 8; nj++)
                    mma16816(acc1[mi][nj], afr[mi],
                             bfr[nj >> 1][(nj & 1) * 2 + 0],
                             bfr[nj >> 1][(nj & 1) * 2 + 1]);
        }
        __syncthreads();

        const int wn1b = (wid >> 1) * 64;
#pragma unroll
        for (int mi = 0; mi < 4; mi++)
#pragma unroll
            for (int nj = 0; nj < 8; nj++) {
                int r0 = wm + mi * 16 + (lane >> 2);
                int n0 = wn1b + nj * 8 + (lane & 3) * 2;
                float g0 = gelu_f(acc1[mi][nj][0]);
                float g1 = gelu_f(acc1[mi][nj][1]);
                float g2 = gelu_f(acc1[mi][nj][2]);
                float g3 = gelu_f(acc1[mi][nj][3]);
                uint32_t hi0 = pack_h2(g0, g1);
                uint32_t hi1 = pack_h2(g2, g3);
                int ch = n0 >> 3, within = (n0 & 7) * 2;
                int ph0 = (ch & ~7) | ((ch & 7) ^ (r0 & 7));
                int ph1 = (ch & ~7) | ((ch & 7) ^ ((r0 + 8) & 7));
                *(uint32_t*)(smem + r0 * 512 + ph0 * 16 + within) = hi0;
                *(uint32_t*)(smem + (r0 + 8) * 512 + ph1 * 16 + within) = hi1;
            }
    }
    __syncthreads();

    float acc2[4][2][4] = {};
    const int wn2 = (wid >> 1) * 16;
#pragma unroll
    for (int ks = 0; ks < 16; ks++) {
        uint32_t afr[4][4];
#pragma unroll
        for (int mi = 0; mi < 4; mi++) {
            int rr = wm + mi * 16 + (lane & 15);
            int cu = ks * 2 + (lane >> 4);
            int ph = (cu & ~7) | ((cu & 7) ^ (rr & 7));
            ldsm4(afr[mi], HS + rr * 512 + ph * 16);
        }
        uint32_t bfr[4];
        {
            int rr = wn2 + (lane & 7) + ((lane >> 4) * 8);
            int cu = ks * 2 + ((lane >> 3) & 1);
            int ph = (cu & ~7) | ((cu & 7) ^ (rr & 7));
            ldsm4(bfr, W2S + rr * 512 + ph * 16);
        }
#pragma unroll
        for (int mi = 0; mi < 4; mi++)
#pragma unroll
            for (int nj = 0; nj < 2; nj++)
                mma16816(acc2[mi][nj], afr[mi], bfr[nj * 2], bfr[nj * 2 + 1]);
    }

#pragma unroll
    for (int mi = 0; mi < 4; mi++)
#pragma unroll
        for (int nj = 0; nj < 2; nj++) {
            int r0 = wm + mi * 16 + (lane >> 2);
            int n0 = wn2 + nj * 8 + (lane & 3) * 2;
#pragma unroll
            for (int h = 0; h < 2; h++) {
                int g = rt * 128 + r0 + h * 8;
                float* p = xb + ((size_t)(g >> 2) * 32 + t * 4 + (g & 3)) * 64 + n0;
                float2 old = *(float2*)p;
                old.x += lam * acc2[mi][nj][h * 2 + 0];
                old.y += lam * acc2[mi][nj][h * 2 + 1];
                *(float2*)p = old;
            }
        }
}

// ---------------------------------------------------------------------------
// LayerNorm fused with fp16 conversion
// ---------------------------------------------------------------------------
__global__ void ln_kernel(const float* __restrict__ x,
                          const float* __restrict__ g,
                          const float* __restrict__ b,
                          __half* __restrict__ Ah) {
    __shared__ float red[256];
    const int s = blockIdx.x, tid = threadIdx.x;
    const float4* row = (const float4*)(x + (size_t)s * D_DIM);
    float4 v = row[tid];
    red[tid] = v.x + v.y + v.z + v.w;
    __syncthreads();
    for (int o = 128; o > 0; o >>= 1) {
        if (tid < o) red[tid] += red[tid + o];
        __syncthreads();
    }
    float mu = red[0] * (1.0f / 1024.0f);
    __syncthreads();
    float dx = v.x - mu, dy = v.y - mu, dz = v.z - mu, dw = v.w - mu;
    red[tid] = dx * dx + dy * dy + dz * dz + dw * dw;
    __syncthreads();
    for (int o = 128; o > 0; o >>= 1) {
        if (tid < o) red[tid] += red[tid + o];
        __syncthreads();
    }
    float rstd = rsqrtf(red[0] * (1.0f / 1024.0f) + 1e-5f);
    float4 gg = ((const float4*)g)[tid];
    float4 bb = ((const float4*)b)[tid];
    float ox = dx * rstd * gg.x + bb.x;
    float oy = dy * rstd * gg.y + bb.y;
    float oz = dz * rstd * gg.z + bb.z;
    float ow = dw * rstd * gg.w + bb.w;
    uint2 H;
    H.x = pack_h2(ox, oy);
    H.y = pack_h2(oz, ow);
    ((uint2*)(Ah + (size_t)s * D_DIM))[tid] = H;
}

// ---------------------------------------------------------------------------
// Deterministic aux reduction
// ---------------------------------------------------------------------------
__global__ void aux_kernel(const float* __restrict__ pcm, float* __restrict__ out) {
    __shared__ float red[256];
    const int tid = threadIdx.x;
    float s = 0.0f;
    for (int i = tid; i < 2 * S_TOT * NB; i += 256) s += pcm[i];
    red[tid] = s;
    __syncthreads();
    for (int o = 128; o > 0; o >>= 1) {
        if (tid < o) red[tid] += red[tid + o];
        __syncthreads();
    }
    if (tid == 0) out[0] = 0.1f * red[0] / 262144.0f;
}

// ---------------------------------------------------------------------------
extern "C" void kernel_launch(void* const* d_in, const int* in_sizes, int n_in,
                              void* d_out, int out_size) {
    const int*   ids  = (const int*)d_in[0];
    const float* emb  = (const float*)d_in[1];
    const float* pos  = (const float*)d_in[2];
    const float* fo_w = (const float*)d_in[3];
    const float* fo_b = (const float*)d_in[4];
    const float* W1   = (const float*)d_in[5];
    const float* W2   = (const float*)d_in[6];
    const float* Wz   = (const float*)d_in[7];
    const float* fi_w = (const float*)d_in[8];
    const float* fi_b = (const float*)d_in[9];
    const float* ln_g = (const float*)d_in[10];
    const float* ln_b = (const float*)d_in[11];
    const float* lamp = (const float*)d_in[12];
    float* out = (float*)d_out;

    float *x, *xb, *zhat, *pcm;
    __half *Ah, *Bh, *Axo, *Bfo, *Axi, *Bfi, *W1p, *W2p;
    cudaGetSymbolAddress((void**)&x,    g_x);
    cudaGetSymbolAddress((void**)&xb,   g_xb);
    cudaGetSymbolAddress((void**)&zhat, g_zhat);
    cudaGetSymbolAddress((void**)&pcm,  g_pcm);
    cudaGetSymbolAddress((void**)&Ah,   g_Ah);
    cudaGetSymbolAddress((void**)&Bh,   g_Bh);
    cudaGetSymbolAddress((void**)&Axo,  g_Axo);
    cudaGetSymbolAddress((void**)&Bfo,  g_Bfo);
    cudaGetSymbolAddress((void**)&Axi,  g_Axi);
    cudaGetSymbolAddress((void**)&Bfi,  g_Bfi);
    cudaGetSymbolAddress((void**)&W1p,  g_W1p);
    cudaGetSymbolAddress((void**)&W2p,  g_W2p);

    cudaFuncSetAttribute(gemm_hmma, cudaFuncAttributeMaxDynamicSharedMemorySize,
                         HSMEM);
    cudaFuncSetAttribute(gemm_hmma_m256,
                         cudaFuncAttributeMaxDynamicSharedMemorySize, M256_SMEM);
    cudaFuncSetAttribute(mlp_tc, cudaFuncAttributeMaxDynamicSharedMemorySize,
                         MLPTC_SMEM);

    // 1. embed (fused fan_out A-split) + weight conversions
    embed_split<<<S_TOT, 256>>>(ids, emb, pos, Axo);
    conv_h<<<V_DIM, 256>>>(emb, Bh);
    convBT<<<dim3(D_DIM / 32, T_DIM / 32), 256>>>(fo_w, Bfo, D_DIM, T_DIM);
    convBT<<<dim3(T_DIM / 32, D_DIM / 32), 256>>>(fi_w, Bfi, T_DIM, D_DIM);
    convW1p<<<512, 256>>>(W1, W1p);
    convW2p<<<512, 256>>>(W2, W2p);

    // 2. fan_out (HMMA 2-term A, plain B with k-wrap)
    gemm_hmma<<<dim3(S_TOT / 128, T_DIM / 128), 256, HSMEM>>>(
        Axo, Bfo, fo_b, xb, 2 * D_DIM, D_DIM, T_DIM, 2 * D_DIM / 64, D_DIM - 1);

    // 3. refine passes
    for (int r = 0; r < 3; r++) {
        mlp_tc<<<dim3(128, NB), 256, MLPTC_SMEM>>>(xb, W1p, W2p, Wz, zhat, pcm,
                                                   lamp, r);
    }

    // 4. fan_in (HMMA 2-term A, plain B with k-wrap)
    convA2<<<S_TOT, 256>>>(xb, Axi, T_DIM);
    gemm_hmma<<<dim3(S_TOT / 128, D_DIM / 128), 256, HSMEM>>>(
        Axi, Bfi, fi_b, x, 2 * T_DIM, T_DIM, D_DIM, 2 * T_DIM / 64, T_DIM - 1);

    // 5. layernorm (fused fp16 output)
    ln_kernel<<<S_TOT, 256>>>(x, ln_g, ln_b, Ah);

    // 6. logits (HMMA plain fp16, 256x128 tile — halved B L2 traffic)
    gemm_hmma_m256<<<dim3(S_TOT / 256, V_DIM / 128), 512, M256_SMEM>>>(
        Ah, Bh, out, 1024, 1024, V_DIM, 16);

    // 7. aux loss
    if (out_size > S_TOT * V_DIM) {
        aux_kernel<<<1, 256>>>(pcm, out + (size_t)S_TOT * V_DIM);
    }
}

// round 13
// speedup vs baseline: 1.1164x; 1.1164x over previous
#include <cuda_runtime.h>
#include <cuda_fp16.h>
#include <stdint.h>
#include <math.h>

// Problem dims
#define S_TOT 4096     // BS*N
#define D_DIM 1024
#define T_DIM 2048
#define V_DIM 32000
#define NB 8

// Scratch (device globals — allocation-free rule)
__device__ float g_x[S_TOT * D_DIM];
__device__ float g_xb[S_TOT * T_DIM];
__device__ float g_pcm[S_TOT * NB];              // combined r1+r2 partials
__device__ __half g_Ah[(size_t)S_TOT * 1024];    // logits A plain fp16
__device__ __half g_Bh[(size_t)V_DIM * 1024];    // emb fp16
__device__ __half g_Axo[(size_t)S_TOT * 2048];   // fan_out A 2-term (hi|lo)
__device__ __half g_Bfo[(size_t)T_DIM * 1024];   // fo_w^T plain fp16
__device__ __half g_Axi[(size_t)S_TOT * 4096];   // fan_in A 2-term
__device__ __half g_Bfi[(size_t)D_DIM * 2048];   // fi_w^T plain fp16
__device__ __half g_W1p[NB * 256 * 64];
__device__ __half g_W2p[NB * 64 * 256];

__device__ __forceinline__ uint32_t smem_u32(const void* p) {
    uint32_t a;
    asm("{ .reg .u64 t; cvta.to.shared.u64 t, %1; cvt.u32.u64 %0, t; }"
        : "=r"(a) : "l"(p));
    return a;
}
__device__ __forceinline__ void ldsm4(uint32_t* r, uint32_t addr) {
    asm volatile("ldmatrix.sync.aligned.m8n8.x4.shared.b16 {%0,%1,%2,%3}, [%4];"
                 : "=r"(r[0]), "=r"(r[1]), "=r"(r[2]), "=r"(r[3]) : "r"(addr));
}
__device__ __forceinline__ void mma16816(float* c, const uint32_t* a,
                                         uint32_t b0, uint32_t b1) {
    asm volatile(
        "mma.sync.aligned.m16n8k16.row.col.f32.f16.f16.f32 "
        "{%0,%1,%2,%3}, {%4,%5,%6,%7}, {%8,%9}, {%0,%1,%2,%3};"
        : "+f"(c[0]), "+f"(c[1]), "+f"(c[2]), "+f"(c[3])
        : "r"(a[0]), "r"(a[1]), "r"(a[2]), "r"(a[3]), "r"(b0), "r"(b1));
}
__device__ __forceinline__ float gelu_f(float v) {
    float u = 0.7978845608028654f * (v + 0.044715f * v * v * v);
    float th;
    asm("tanh.approx.f32 %0, %1;" : "=f"(th) : "f"(u));
    return 0.5f * v * (1.0f + th);
}
__device__ __forceinline__ uint32_t pack_h2(float a, float b) {
    __half ha = __float2half_rn(a), hb = __float2half_rn(b);
    return (uint32_t)__half_as_ushort(ha) | ((uint32_t)__half_as_ushort(hb) << 16);
}

// ---------------------------------------------------------------------------
// Conversions
// ---------------------------------------------------------------------------
__global__ void conv_h(const float* __restrict__ src, __half* __restrict__ dst) {
    size_t i = (size_t)blockIdx.x * 256 + threadIdx.x;
    float4 v = ((const float4*)src)[i];
    uint2 H;
    H.x = pack_h2(v.x, v.y); H.y = pack_h2(v.z, v.w);
    ((uint2*)dst)[i] = H;
}

__global__ void convBT(const float* __restrict__ src, __half* __restrict__ dst,
                       int K, int N) {
    __shared__ float tile[32][33];
    int k0 = blockIdx.x * 32, n0 = blockIdx.y * 32;
    int tx = threadIdx.x & 31, ty = threadIdx.x >> 5;
    for (int i = ty; i < 32; i += 8)
        tile[i][tx] = src[(size_t)(k0 + i) * N + n0 + tx];
    __syncthreads();
    for (int i = ty; i < 32; i += 8) {
        int n = n0 + i;
        dst[(size_t)n * K + k0 + tx] = __float2half_rn(tile[tx][i]);
    }
}

__global__ void convW1p(const float* __restrict__ W1, __half* __restrict__ W1p) {
    int idx = blockIdx.x * 256 + threadIdx.x;
    int t = idx >> 14, rem = idx & 16383;
    int rr = rem >> 6, ph = (rem >> 3) & 7, j = rem & 7;
    int k = ((ph ^ (rr & 7)) << 3) | j;
    W1p[idx] = __float2half_rn(W1[((size_t)t * 64 + k) * 256 + rr]);
}
__global__ void convW2p(const float* __restrict__ W2, __half* __restrict__ W2p) {
    int idx = blockIdx.x * 256 + threadIdx.x;
    int t = idx >> 14, rem = idx & 16383;
    int rr = rem >> 8, ph = (rem >> 3) & 31, j = rem & 7;
    int c = (ph & ~7) | ((ph & 7) ^ (rr & 7));
    int k = (c << 3) | j;
    W2p[idx] = __float2half_rn(W2[((size_t)t * 256 + k) * 64 + rr]);
}

// ---------------------------------------------------------------------------
// Embedding gather + pos add, fused with fan_out A 2-term split (hi|lo)
// ---------------------------------------------------------------------------
__global__ void embed_split(const int* __restrict__ ids,
                            const float* __restrict__ emb,
                            const float* __restrict__ pos,
                            __half* __restrict__ Axo) {
    int s = blockIdx.x;
    int q = threadIdx.x;
    int id = ids[s];
    float4 e = ((const float4*)(emb + (size_t)id * D_DIM))[q];
    float4 p = ((const float4*)(pos + (size_t)(s & 1023) * D_DIM))[q];
    float vx = e.x + p.x, vy = e.y + p.y, vz = e.z + p.z, vw = e.w + p.w;
    __half h0 = __float2half_rn(vx), h1 = __float2half_rn(vy);
    __half h2 = __float2half_rn(vz), h3 = __float2half_rn(vw);
    uint2 H, L;
    H.x = pack_h2(vx, vy); H.y = pack_h2(vz, vw);
    L.x = pack_h2(vx - __half2float(h0), vy - __half2float(h1));
    L.y = pack_h2(vz - __half2float(h2), vw - __half2float(h3));
    __half* base = Axo + (size_t)s * 2048 + q * 4;
    *(uint2*)base = H;
    *(uint2*)(base + 1024) = L;
}

// ---------------------------------------------------------------------------
// HMMA fp16 GEMM, 128x128 tile, 3-stage pipeline (fan_out / fan_in / logits)
// ---------------------------------------------------------------------------
#define HBUF 32768
#define HSMEM (3 * HBUF)

__global__ __launch_bounds__(256) void gemm_hmma(
    const __half* __restrict__ A, const __half* __restrict__ B,
    const float* __restrict__ bias, float* __restrict__ C,
    int ldA, int ldB, int N, int nch, int bkmask) {
    extern __shared__ __align__(128) char smem[];
    const uint32_t sb = smem_u32(smem);
    const int tid = threadIdx.x, lane = tid & 31, wid = tid >> 5;
    const int bm = blockIdx.x * 128, bn = blockIdx.y * 128;
    const int wm = (wid & 1) * 64, wn = (wid >> 1) * 32;

    float acc[4][4][4] = {};

    auto issue = [&](int ch, int buf) {
        int k0 = ch * 64;
        int bk = k0 & bkmask;
        uint32_t abase = sb + buf * HBUF;
        uint32_t bbase = abase + 16384;
#pragma unroll
        for (int i = 0; i < 4; i++) {
            int idx = tid + 256 * i;
            int r = idx >> 3, c = idx & 7;
            uint32_t off = (uint32_t)(r * 128 + ((c ^ (r & 7)) * 16));
            const __half* gp = A + (size_t)(bm + r) * ldA + k0 + c * 8;
            asm volatile("cp.async.cg.shared.global [%0], [%1], 16;"
                         :: "r"(abase + off), "l"(gp));
        }
#pragma unroll
        for (int i = 0; i < 4; i++) {
            int idx = tid + 256 * i;
            int r = idx >> 3, c = idx & 7;
            uint32_t off = (uint32_t)(r * 128 + ((c ^ (r & 7)) * 16));
            const __half* gp = B + (size_t)(bn + r) * ldB + bk + c * 8;
            asm volatile("cp.async.cg.shared.global [%0], [%1], 16;"
                         :: "r"(bbase + off), "l"(gp));
        }
        asm volatile("cp.async.commit_group;" ::: "memory");
    };

    issue(0, 0);
    issue(1, 1);

    int buf = 0;
    for (int ch = 0; ch < nch; ch++) {
        if (ch + 1 < nch) {
            asm volatile("cp.async.wait_group 1;" ::: "memory");
        } else {
            asm volatile("cp.async.wait_group 0;" ::: "memory");
        }
        __syncthreads();
        if (ch + 2 < nch) {
            int nb = buf + 2;
            if (nb >= 3) nb -= 3;
            issue(ch + 2, nb);
        }

        uint32_t abase = sb + buf * HBUF;
        uint32_t bbase = abase + 16384;
#pragma unroll
        for (int ks = 0; ks < 4; ks++) {
            uint32_t afr[4][4];
#pragma unroll
            for (int mi = 0; mi < 4; mi++) {
                int r = wm + mi * 16 + (lane & 15);
                int cu = ks * 2 + (lane >> 4);
                uint32_t addr = abase + r * 128 + ((cu ^ (r & 7)) * 16);
                ldsm4(afr[mi], addr);
            }
            uint32_t bfr[2][4];
#pragma unroll
            for (int p = 0; p < 2; p++) {
                int r = wn + p * 16 + (lane & 7) + ((lane >> 4) * 8);
                int cu = ks * 2 + ((lane >> 3) & 1);
                uint32_t addr = bbase + r * 128 + ((cu ^ (r & 7)) * 16);
                ldsm4(bfr[p], addr);
            }
#pragma unroll
            for (int mi = 0; mi < 4; mi++)
#pragma unroll
                for (int nj = 0; nj < 4; nj++)
                    mma16816(acc[mi][nj], afr[mi],
                             bfr[nj >> 1][(nj & 1) * 2 + 0],
                             bfr[nj >> 1][(nj & 1) * 2 + 1]);
        }
        if (++buf == 3) buf = 0;
    }

#pragma unroll
    for (int mi = 0; mi < 4; mi++) {
#pragma unroll
        for (int nj = 0; nj < 4; nj++) {
            int row = bm + wm + mi * 16 + (lane >> 2);
            int col = bn + wn + nj * 8 + (lane & 3) * 2;
            float b0 = bias ? bias[col] : 0.0f;
            float b1 = bias ? bias[col + 1] : 0.0f;
            float2 v0 = make_float2(acc[mi][nj][0] + b0, acc[mi][nj][1] + b1);
            float2 v1 = make_float2(acc[mi][nj][2] + b0, acc[mi][nj][3] + b1);
            *(float2*)(C + (size_t)row * N + col) = v0;
            *(float2*)(C + (size_t)(row + 8) * N + col) = v1;
        }
    }
}

// ---------------------------------------------------------------------------
// Fully-fused 3-pass refine: X resident in smem, zhat in smem,
// final pass writes fan_in A-split (Axi) directly. xb never written.
// Smem layout (bytes):
//   XF  [0,      32768): X fp32, row stride 256B (128 rows x 64 f32)
//   XS  [32768,  65536): X split fp16 2-term, row stride 256B
//   HS  [65536, 131072): H plain fp16, row stride 512B
//   W1S [131072,163840)  W2S [163840,196608)
//   WZ  [196608,212992): Wz fp32   Z [212992,221184)  ZH [221184,229376)
// ---------------------------------------------------------------------------
#define XFo 0
#define XSo 32768
#define HSo 65536
#define W1o 131072
#define W2o 163840
#define WZo 196608
#define Zo  212992
#define ZHo 221184
#define MLP3_SMEM 229376

__global__ __launch_bounds__(256) void mlp3_tc(
    const float* __restrict__ xb, const __half* __restrict__ W1p,
    const __half* __restrict__ W2p, const float* __restrict__ Wz,
    __half* __restrict__ Axi, float* __restrict__ pcm,
    const float* __restrict__ lam_logit) {
    extern __shared__ __align__(128) char smem[];
    const uint32_t sb = smem_u32(smem);
    float* wzsp = (float*)(smem + WZo);
    float* zsp  = (float*)(smem + Zo);
    float* zhsp = (float*)(smem + ZHo);
    const int tid = threadIdx.x, lane = tid & 31, wid = tid >> 5;
    const int t = blockIdx.y, rt = blockIdx.x;
    const int wm = (wid & 1) * 64;
    const float lam = 1.0f / (1.0f + expf(-lam_logit[0]));

    // async-load weights
    {
        const __half* w1g = W1p + (size_t)t * 16384;
        const __half* w2g = W2p + (size_t)t * 16384;
        const float* wzg = Wz + (size_t)t * 4096;
#pragma unroll
        for (int i = 0; i < 8; i++) {
            int idx = tid + 256 * i;
            asm volatile("cp.async.cg.shared.global [%0], [%1], 16;"
                         :: "r"(sb + W1o + idx * 16), "l"(w1g + idx * 8));
        }
#pragma unroll
        for (int i = 0; i < 8; i++) {
            int idx = tid + 256 * i;
            asm volatile("cp.async.cg.shared.global [%0], [%1], 16;"
                         :: "r"(sb + W2o + idx * 16), "l"(w2g + idx * 8));
        }
#pragma unroll
        for (int i = 0; i < 4; i++) {
            int idx = tid + 256 * i;
            asm volatile("cp.async.cg.shared.global [%0], [%1], 16;"
                         :: "r"(sb + WZo + idx * 16), "l"(wzg + idx * 4));
        }
        asm volatile("cp.async.commit_group;" ::: "memory");
    }

    // Initial X load: fp32 copy into XF + 2-term split into XS
#pragma unroll
    for (int i = 0; i < 4; i++) {
        int idx = tid + 256 * i;
        int lr = idx >> 3, c = idx & 7;
        int g = rt * 128 + lr;
        const float* xp = xb + ((size_t)(g >> 2) * 32 + t * 4 + (g & 3)) * 64 + c * 8;
        float4 v0 = *(const float4*)xp;
        float4 v1 = *(const float4*)(xp + 4);
        *(float4*)(smem + XFo + lr * 256 + c * 32) = v0;
        *(float4*)(smem + XFo + lr * 256 + c * 32 + 16) = v1;
        float vv[8] = {v0.x, v0.y, v0.z, v0.w, v1.x, v1.y, v1.z, v1.w};
        uint4 Hh, Ll;
        uint32_t* hw = (uint32_t*)&Hh;
        uint32_t* lw = (uint32_t*)&Ll;
#pragma unroll
        for (int j = 0; j < 4; j++) {
            float a = vv[2 * j], b = vv[2 * j + 1];
            __half ha = __float2half_rn(a), hb = __float2half_rn(b);
            hw[j] = (uint32_t)__half_as_ushort(ha) |
                    ((uint32_t)__half_as_ushort(hb) << 16);
            lw[j] = pack_h2(a - __half2float(ha), b - __half2float(hb));
        }
        int phh = c ^ (lr & 7);
        *(uint4*)(smem + XSo + lr * 256 + phh * 16) = Hh;
        *(uint4*)(smem + XSo + lr * 256 + (8 + phh) * 16) = Ll;
    }
    asm volatile("cp.async.wait_group 0;" ::: "memory");
    __syncthreads();  // XF/XS + weights visible

    const int s_loc = tid >> 3;
    const int e0 = (tid & 7) * 8;
    const int st = (rt * 32 + s_loc) * 8 + t;
    float sq_acc = 0.0f;

#pragma unroll 1
    for (int r = 0; r < 3; r++) {
        const float lamr = (r == 0) ? 1.0f : lam;

        // ---- z = mean_c (from fp32 XF) ----
        float zv[8];
        {
            float acc[8] = {};
#pragma unroll
            for (int c = 0; c < 4; c++) {
                const float4* xf =
                    (const float4*)(smem + XFo + (s_loc * 4 + c) * 256 + e0 * 4);
                float4 a = xf[0], b = xf[1];
                acc[0] += a.x; acc[1] += a.y; acc[2] += a.z; acc[3] += a.w;
                acc[4] += b.x; acc[5] += b.y; acc[6] += b.z; acc[7] += b.w;
            }
#pragma unroll
            for (int j = 0; j < 8; j++) {
                zv[j] = 0.25f * acc[j];
                zsp[s_loc * 64 + e0 + j] = zv[j];
            }
        }
        // ---- pcm accumulate (r>0) ----
        if (r > 0) {
#pragma unroll
            for (int j = 0; j < 8; j++) {
                float diff = zhsp[s_loc * 64 + e0 + j] - zv[j];
                sq_acc = fmaf(diff, diff, sq_acc);
            }
        }
        if (r == 2) {  // reduce over the 8 lanes of this group, write once
            float sq = sq_acc;
            sq += __shfl_down_sync(0xffffffffu, sq, 4, 8);
            sq += __shfl_down_sync(0xffffffffu, sq, 2, 8);
            sq += __shfl_down_sync(0xffffffffu, sq, 1, 8);
            if ((tid & 7) == 0) pcm[st] = sq;
        }
        // ---- zhat = z @ Wz (skip on last pass) ----
        if (r < 2) {
            __syncwarp();
            const float* zr = zsp + s_loc * 64;
            float acc[8] = {};
            for (int d = 0; d < 64; d++) {
                float z = zr[d];
                const float* wr = wzsp + d * 64 + e0;
#pragma unroll
                for (int j = 0; j < 8; j++) acc[j] = fmaf(z, wr[j], acc[j]);
            }
#pragma unroll
            for (int j = 0; j < 8; j++) zhsp[s_loc * 64 + e0 + j] = acc[j];
        }

        // ---- Phase 1: H = gelu(X2 @ W1h), warp tile 64x64 ----
        {
            float acc1[4][8][4] = {};
            const int wn1 = (wid >> 1) * 64;
#pragma unroll
            for (int ks = 0; ks < 8; ks++) {
                uint32_t afr[4][4];
#pragma unroll
                for (int mi = 0; mi < 4; mi++) {
                    int rr = wm + mi * 16 + (lane & 15);
                    int cu = ks * 2 + (lane >> 4);
                    int ph = (cu & 8) | ((cu & 7) ^ (rr & 7));
                    ldsm4(afr[mi], sb + XSo + rr * 256 + ph * 16);
                }
                uint32_t bfr[4][4];
#pragma unroll
                for (int p = 0; p < 4; p++) {
                    int rr = wn1 + p * 16 + (lane & 7) + ((lane >> 4) * 8);
                    int cu = (ks * 2 + ((lane >> 3) & 1)) & 7;
                    int ph = cu ^ (rr & 7);
                    ldsm4(bfr[p], sb + W1o + rr * 128 + ph * 16);
                }
#pragma unroll
                for (int mi = 0; mi < 4; mi++)
#pragma unroll
                    for (int nj = 0; nj < 8; nj++)
                        mma16816(acc1[mi][nj], afr[mi],
                                 bfr[nj >> 1][(nj & 1) * 2 + 0],
                                 bfr[nj >> 1][(nj & 1) * 2 + 1]);
            }
            // gelu -> HS (plain fp16) — HS disjoint from XS/W1S, no sync needed
#pragma unroll
            for (int mi = 0; mi < 4; mi++)
#pragma unroll
                for (int nj = 0; nj < 8; nj++) {
                    int r0 = wm + mi * 16 + (lane >> 2);
                    int n0 = wn1 + nj * 8 + (lane & 3) * 2;
                    float g0 = gelu_f(acc1[mi][nj][0]);
                    float g1 = gelu_f(acc1[mi][nj][1]);
                    float g2 = gelu_f(acc1[mi][nj][2]);
                    float g3 = gelu_f(acc1[mi][nj][3]);
                    uint32_t hi0 = pack_h2(g0, g1);
                    uint32_t hi1 = pack_h2(g2, g3);
                    int ch = n0 >> 3, within = (n0 & 7) * 2;
                    int ph0 = (ch & ~7) | ((ch & 7) ^ (r0 & 7));
                    int ph1 = (ch & ~7) | ((ch & 7) ^ ((r0 + 8) & 7));
                    *(uint32_t*)(smem + HSo + r0 * 512 + ph0 * 16 + within) = hi0;
                    *(uint32_t*)(smem + HSo + (r0 + 8) * 512 + ph1 * 16 + within) = hi1;
                }
        }
        __syncthreads();  // HS complete

        // ---- Phase 2: delta = H @ W2h, warp tile 64x16 ----
        float acc2[4][2][4] = {};
        const int wn2 = (wid >> 1) * 16;
#pragma unroll
        for (int ks = 0; ks < 16; ks++) {
            uint32_t afr[4][4];
#pragma unroll
            for (int mi = 0; mi < 4; mi++) {
                int rr = wm + mi * 16 + (lane & 15);
                int cu = ks * 2 + (lane >> 4);
                int ph = (cu & ~7) | ((cu & 7) ^ (rr & 7));
                ldsm4(afr[mi], sb + HSo + rr * 512 + ph * 16);
            }
            uint32_t bfr[4];
            {
                int rr = wn2 + (lane & 7) + ((lane >> 4) * 8);
                int cu = ks * 2 + ((lane >> 3) & 1);
                int ph = (cu & ~7) | ((cu & 7) ^ (rr & 7));
                ldsm4(bfr, sb + W2o + rr * 512 + ph * 16);
            }
#pragma unroll
            for (int mi = 0; mi < 4; mi++)
#pragma unroll
                for (int nj = 0; nj < 2; nj++)
                    mma16816(acc2[mi][nj], afr[mi], bfr[nj * 2], bfr[nj * 2 + 1]);
        }

        // ---- Epilogue ----
#pragma unroll
        for (int mi = 0; mi < 4; mi++)
#pragma unroll
            for (int nj = 0; nj < 2; nj++) {
                int n0 = wn2 + nj * 8 + (lane & 3) * 2;
#pragma unroll
                for (int h = 0; h < 2; h++) {
                    int lr = wm + mi * 16 + (lane >> 2) + h * 8;
                    float* xf = (float*)(smem + XFo + lr * 256 + n0 * 4);
                    float nx = xf[0] + lamr * acc2[mi][nj][h * 2 + 0];
                    float ny = xf[1] + lamr * acc2[mi][nj][h * 2 + 1];
                    __half hx = __float2half_rn(nx), hy = __float2half_rn(ny);
                    uint32_t hiw = (uint32_t)__half_as_ushort(hx) |
                                   ((uint32_t)__half_as_ushort(hy) << 16);
                    uint32_t low = pack_h2(nx - __half2float(hx),
                                           ny - __half2float(hy));
                    if (r < 2) {
                        xf[0] = nx; xf[1] = ny;
                        int ph = (n0 >> 3) ^ (lr & 7);
                        *(uint32_t*)(smem + XSo + lr * 256 + ph * 16 +
                                     (n0 & 7) * 2) = hiw;
                        *(uint32_t*)(smem + XSo + lr * 256 + (8 + ph) * 16 +
                                     (n0 & 7) * 2) = low;
                    } else {
                        int g = rt * 128 + lr;
                        size_t base = (size_t)(g >> 2) * 4096 + t * 256 +
                                      (g & 3) * 64 + n0;
                        *(uint32_t*)(Axi + base) = hiw;
                        *(uint32_t*)(Axi + base + 2048) = low;
                    }
                }
            }
        __syncthreads();  // XF/XS updates visible for next pass
    }
}

// ---------------------------------------------------------------------------
// LayerNorm fused with fp16 conversion
// ---------------------------------------------------------------------------
__global__ void ln_kernel(const float* __restrict__ x,
                          const float* __restrict__ g,
                          const float* __restrict__ b,
                          __half* __restrict__ Ah) {
    __shared__ float red[256];
    const int s = blockIdx.x, tid = threadIdx.x;
    const float4* row = (const float4*)(x + (size_t)s * D_DIM);
    float4 v = row[tid];
    red[tid] = v.x + v.y + v.z + v.w;
    __syncthreads();
    for (int o = 128; o > 0; o >>= 1) {
        if (tid < o) red[tid] += red[tid + o];
        __syncthreads();
    }
    float mu = red[0] * (1.0f / 1024.0f);
    __syncthreads();
    float dx = v.x - mu, dy = v.y - mu, dz = v.z - mu, dw = v.w - mu;
    red[tid] = dx * dx + dy * dy + dz * dz + dw * dw;
    __syncthreads();
    for (int o = 128; o > 0; o >>= 1) {
        if (tid < o) red[tid] += red[tid + o];
        __syncthreads();
    }
    float rstd = rsqrtf(red[0] * (1.0f / 1024.0f) + 1e-5f);
    float4 gg = ((const float4*)g)[tid];
    float4 bb = ((const float4*)b)[tid];
    float ox = dx * rstd * gg.x + bb.x;
    float oy = dy * rstd * gg.y + bb.y;
    float oz = dz * rstd * gg.z + bb.z;
    float ow = dw * rstd * gg.w + bb.w;
    uint2 H;
    H.x = pack_h2(ox, oy);
    H.y = pack_h2(oz, ow);
    ((uint2*)(Ah + (size_t)s * D_DIM))[tid] = H;
}

// ---------------------------------------------------------------------------
// Deterministic aux reduction (combined r1+r2 partials)
// ---------------------------------------------------------------------------
__global__ void aux_kernel(const float* __restrict__ pcm, float* __restrict__ out) {
    __shared__ float red[256];
    const int tid = threadIdx.x;
    float s = 0.0f;
    for (int i = tid; i < S_TOT * NB; i += 256) s += pcm[i];
    red[tid] = s;
    __syncthreads();
    for (int o = 128; o > 0; o >>= 1) {
        if (tid < o) red[tid] += red[tid + o];
        __syncthreads();
    }
    if (tid == 0) out[0] = 0.1f * red[0] / 262144.0f;
}

// ---------------------------------------------------------------------------
extern "C" void kernel_launch(void* const* d_in, const int* in_sizes, int n_in,
                              void* d_out, int out_size) {
    const int*   ids  = (const int*)d_in[0];
    const float* emb  = (const float*)d_in[1];
    const float* pos  = (const float*)d_in[2];
    const float* fo_w = (const float*)d_in[3];
    const float* fo_b = (const float*)d_in[4];
    const float* W1   = (const float*)d_in[5];
    const float* W2   = (const float*)d_in[6];
    const float* Wz   = (const float*)d_in[7];
    const float* fi_w = (const float*)d_in[8];
    const float* fi_b = (const float*)d_in[9];
    const float* ln_g = (const float*)d_in[10];
    const float* ln_b = (const float*)d_in[11];
    const float* lamp = (const float*)d_in[12];
    float* out = (float*)d_out;

    float *x, *xb, *pcm;
    __half *Ah, *Bh, *Axo, *Bfo, *Axi, *Bfi, *W1p, *W2p;
    cudaGetSymbolAddress((void**)&x,    g_x);
    cudaGetSymbolAddress((void**)&xb,   g_xb);
    cudaGetSymbolAddress((void**)&pcm,  g_pcm);
    cudaGetSymbolAddress((void**)&Ah,   g_Ah);
    cudaGetSymbolAddress((void**)&Bh,   g_Bh);
    cudaGetSymbolAddress((void**)&Axo,  g_Axo);
    cudaGetSymbolAddress((void**)&Bfo,  g_Bfo);
    cudaGetSymbolAddress((void**)&Axi,  g_Axi);
    cudaGetSymbolAddress((void**)&Bfi,  g_Bfi);
    cudaGetSymbolAddress((void**)&W1p,  g_W1p);
    cudaGetSymbolAddress((void**)&W2p,  g_W2p);

    cudaFuncSetAttribute(gemm_hmma, cudaFuncAttributeMaxDynamicSharedMemorySize,
                         HSMEM);
    cudaFuncSetAttribute(mlp3_tc, cudaFuncAttributeMaxDynamicSharedMemorySize,
                         MLP3_SMEM);

    // 1. embed (fused fan_out A-split) + weight conversions
    embed_split<<<S_TOT, 256>>>(ids, emb, pos, Axo);
    conv_h<<<V_DIM, 256>>>(emb, Bh);
    convBT<<<dim3(D_DIM / 32, T_DIM / 32), 256>>>(fo_w, Bfo, D_DIM, T_DIM);
    convBT<<<dim3(T_DIM / 32, D_DIM / 32), 256>>>(fi_w, Bfi, T_DIM, D_DIM);
    convW1p<<<512, 256>>>(W1, W1p);
    convW2p<<<512, 256>>>(W2, W2p);

    // 2. fan_out (HMMA 2-term A, plain B with k-wrap)
    gemm_hmma<<<dim3(S_TOT / 128, T_DIM / 128), 256, HSMEM>>>(
        Axo, Bfo, fo_b, xb, 2 * D_DIM, D_DIM, T_DIM, 2 * D_DIM / 64, D_DIM - 1);

    // 3. ALL 3 refine passes in one launch; emits fan_in A-split directly
    mlp3_tc<<<dim3(128, NB), 256, MLP3_SMEM>>>(xb, W1p, W2p, Wz, Axi, pcm, lamp);

    // 4. fan_in (HMMA 2-term A, plain B with k-wrap)
    gemm_hmma<<<dim3(S_TOT / 128, D_DIM / 128), 256, HSMEM>>>(
        Axi, Bfi, fi_b, x, 2 * T_DIM, T_DIM, D_DIM, 2 * T_DIM / 64, T_DIM - 1);

    // 5. layernorm (fused fp16 output)
    ln_kernel<<<S_TOT, 256>>>(x, ln_g, ln_b, Ah);

    // 6. logits (HMMA plain fp16 A, K=1024, 128x128 tile — proven config)
    gemm_hmma<<<dim3(S_TOT / 128, V_DIM / 128), 256, HSMEM>>>(
        Ah, Bh, (const float*)0, out, 1024, 1024, V_DIM, 16, ~0);

    // 7. aux loss
    if (out_size > S_TOT * V_DIM) {
        aux_kernel<<<1, 256>>>(pcm, out + (size_t)S_TOT * V_DIM);
    }
}

// round 14
// speedup vs baseline: 1.1241x; 1.0069x over previous
#include <cuda_runtime.h>
#include <cuda_fp16.h>
#include <stdint.h>
#include <math.h>

// Problem dims
#define S_TOT 4096     // BS*N
#define D_DIM 1024
#define T_DIM 2048
#define V_DIM 32000
#define NB 8

// Scratch (device globals — allocation-free rule)
__device__ float g_x[S_TOT * D_DIM];
__device__ float g_xb[S_TOT * T_DIM];
__device__ float g_pcm[S_TOT * NB];
__device__ __half g_Ah[(size_t)S_TOT * 1024];
__device__ __half g_Bh[(size_t)V_DIM * 1024];
__device__ __half g_Axo[(size_t)S_TOT * 2048];
__device__ __half g_Bfo[(size_t)T_DIM * 1024];
__device__ __half g_Axi[(size_t)S_TOT * 4096];
__device__ __half g_Bfi[(size_t)D_DIM * 2048];
__device__ __half g_W1p[NB * 256 * 64];
__device__ __half g_W2p[NB * 64 * 256];

__device__ __forceinline__ uint32_t smem_u32(const void* p) {
    uint32_t a;
    asm("{ .reg .u64 t; cvta.to.shared.u64 t, %1; cvt.u32.u64 %0, t; }"
        : "=r"(a) : "l"(p));
    return a;
}
__device__ __forceinline__ void ldsm4(uint32_t* r, uint32_t addr) {
    asm volatile("ldmatrix.sync.aligned.m8n8.x4.shared.b16 {%0,%1,%2,%3}, [%4];"
                 : "=r"(r[0]), "=r"(r[1]), "=r"(r[2]), "=r"(r[3]) : "r"(addr));
}
__device__ __forceinline__ void mma16816(float* c, const uint32_t* a,
                                         uint32_t b0, uint32_t b1) {
    asm volatile(
        "mma.sync.aligned.m16n8k16.row.col.f32.f16.f16.f32 "
        "{%0,%1,%2,%3}, {%4,%5,%6,%7}, {%8,%9}, {%0,%1,%2,%3};"
        : "+f"(c[0]), "+f"(c[1]), "+f"(c[2]), "+f"(c[3])
        : "r"(a[0]), "r"(a[1]), "r"(a[2]), "r"(a[3]), "r"(b0), "r"(b1));
}
__device__ __forceinline__ float gelu_f(float v) {
    float u = 0.7978845608028654f * (v + 0.044715f * v * v * v);
    float th;
    asm("tanh.approx.f32 %0, %1;" : "=f"(th) : "f"(u));
    return 0.5f * v * (1.0f + th);
}
__device__ __forceinline__ uint32_t pack_h2(float a, float b) {
    __half ha = __float2half_rn(a), hb = __float2half_rn(b);
    return (uint32_t)__half_as_ushort(ha) | ((uint32_t)__half_as_ushort(hb) << 16);
}

// ---------------------------------------------------------------------------
// MERGED prep kernel: embed_split | conv_h(Bh) | convBT(fo) | convBT(fi) |
// convW1p | convW2p — dispatched by blockIdx.x range (uniform per block).
// ---------------------------------------------------------------------------
#define PREP_EMBED   4096
#define PREP_CONVH   (PREP_EMBED + 32000)     // 36096
#define PREP_BTFO    (PREP_CONVH + 2048)      // 38144
#define PREP_BTFI    (PREP_BTFO + 2048)       // 40192
#define PREP_W1      (PREP_BTFI + 512)        // 40704
#define PREP_TOTAL   (PREP_W1 + 512)          // 41216

__global__ void prep_kernel(
    const int* __restrict__ ids, const float* __restrict__ emb,
    const float* __restrict__ pos, const float* __restrict__ fo_w,
    const float* __restrict__ fi_w, const float* __restrict__ W1,
    const float* __restrict__ W2,
    __half* __restrict__ Axo, __half* __restrict__ Bh,
    __half* __restrict__ Bfo, __half* __restrict__ Bfi,
    __half* __restrict__ W1p, __half* __restrict__ W2p) {
    __shared__ float tile[32][33];
    const int b = blockIdx.x;
    const int tid = threadIdx.x;

    if (b < PREP_EMBED) {
        // ---- embed + pos + fan_out A 2-term split ----
        int s = b;
        int id = ids[s];
        float4 e = ((const float4*)(emb + (size_t)id * D_DIM))[tid];
        float4 p = ((const float4*)(pos + (size_t)(s & 1023) * D_DIM))[tid];
        float vx = e.x + p.x, vy = e.y + p.y, vz = e.z + p.z, vw = e.w + p.w;
        __half h0 = __float2half_rn(vx), h1 = __float2half_rn(vy);
        __half h2 = __float2half_rn(vz), h3 = __float2half_rn(vw);
        uint2 H, L;
        H.x = pack_h2(vx, vy); H.y = pack_h2(vz, vw);
        L.x = pack_h2(vx - __half2float(h0), vy - __half2float(h1));
        L.y = pack_h2(vz - __half2float(h2), vw - __half2float(h3));
        __half* base = Axo + (size_t)s * 2048 + tid * 4;
        *(uint2*)base = H;
        *(uint2*)(base + 1024) = L;
    } else if (b < PREP_CONVH) {
        // ---- emb -> Bh plain fp16 ----
        size_t i = (size_t)(b - PREP_EMBED) * 256 + tid;
        float4 v = ((const float4*)emb)[i];
        uint2 H;
        H.x = pack_h2(v.x, v.y); H.y = pack_h2(v.z, v.w);
        ((uint2*)Bh)[i] = H;
    } else if (b < PREP_BTFO) {
        // ---- fo_w [1024,2048] -> Bfo [2048,1024] fp16 (grid was 32x64) ----
        int bid = b - PREP_CONVH;
        int k0 = (bid & 31) * 32, n0 = (bid >> 5) * 32;
        int tx = tid & 31, ty = tid >> 5;
        for (int i = ty; i < 32; i += 8)
            tile[i][tx] = fo_w[(size_t)(k0 + i) * T_DIM + n0 + tx];
        __syncthreads();
        for (int i = ty; i < 32; i += 8) {
            int n = n0 + i;
            Bfo[(size_t)n * D_DIM + k0 + tx] = __float2half_rn(tile[tx][i]);
        }
    } else if (b < PREP_BTFI) {
        // ---- fi_w [2048,1024] -> Bfi [1024,2048] fp16 (grid was 64x32) ----
        int bid = b - PREP_BTFO;
        int k0 = (bid & 63) * 32, n0 = (bid >> 6) * 32;
        int tx = tid & 31, ty = tid >> 5;
        for (int i = ty; i < 32; i += 8)
            tile[i][tx] = fi_w[(size_t)(k0 + i) * D_DIM + n0 + tx];
        __syncthreads();
        for (int i = ty; i < 32; i += 8) {
            int n = n0 + i;
            Bfi[(size_t)n * T_DIM + k0 + tx] = __float2half_rn(tile[tx][i]);
        }
    } else if (b < PREP_W1) {
        // ---- W1 pre-swizzle ----
        int idx = (b - PREP_BTFI) * 256 + tid;
        int t = idx >> 14, rem = idx & 16383;
        int rr = rem >> 6, ph = (rem >> 3) & 7, j = rem & 7;
        int k = ((ph ^ (rr & 7)) << 3) | j;
        W1p[idx] = __float2half_rn(W1[((size_t)t * 64 + k) * 256 + rr]);
    } else {
        // ---- W2 pre-swizzle ----
        int idx = (b - PREP_W1) * 256 + tid;
        int t = idx >> 14, rem = idx & 16383;
        int rr = rem >> 8, ph = (rem >> 3) & 31, j = rem & 7;
        int c = (ph & ~7) | ((ph & 7) ^ (rr & 7));
        int k = (c << 3) | j;
        W2p[idx] = __float2half_rn(W2[((size_t)t * 256 + k) * 64 + rr]);
    }
}

// ---------------------------------------------------------------------------
// HMMA fp16 GEMM, 128x128 tile, 3-stage pipeline (fan_out / fan_in / logits)
// ---------------------------------------------------------------------------
#define HBUF 32768
#define HSMEM (3 * HBUF)

__global__ __launch_bounds__(256) void gemm_hmma(
    const __half* __restrict__ A, const __half* __restrict__ B,
    const float* __restrict__ bias, float* __restrict__ C,
    int ldA, int ldB, int N, int nch, int bkmask) {
    extern __shared__ __align__(128) char smem[];
    const uint32_t sb = smem_u32(smem);
    const int tid = threadIdx.x, lane = tid & 31, wid = tid >> 5;
    const int bm = blockIdx.x * 128, bn = blockIdx.y * 128;
    const int wm = (wid & 1) * 64, wn = (wid >> 1) * 32;

    float acc[4][4][4] = {};

    auto issue = [&](int ch, int buf) {
        int k0 = ch * 64;
        int bk = k0 & bkmask;
        uint32_t abase = sb + buf * HBUF;
        uint32_t bbase = abase + 16384;
#pragma unroll
        for (int i = 0; i < 4; i++) {
            int idx = tid + 256 * i;
            int r = idx >> 3, c = idx & 7;
            uint32_t off = (uint32_t)(r * 128 + ((c ^ (r & 7)) * 16));
            const __half* gp = A + (size_t)(bm + r) * ldA + k0 + c * 8;
            asm volatile("cp.async.cg.shared.global [%0], [%1], 16;"
                         :: "r"(abase + off), "l"(gp));
        }
#pragma unroll
        for (int i = 0; i < 4; i++) {
            int idx = tid + 256 * i;
            int r = idx >> 3, c = idx & 7;
            uint32_t off = (uint32_t)(r * 128 + ((c ^ (r & 7)) * 16));
            const __half* gp = B + (size_t)(bn + r) * ldB + bk + c * 8;
            asm volatile("cp.async.cg.shared.global [%0], [%1], 16;"
                         :: "r"(bbase + off), "l"(gp));
        }
        asm volatile("cp.async.commit_group;" ::: "memory");
    };

    issue(0, 0);
    issue(1, 1);

    int buf = 0;
    for (int ch = 0; ch < nch; ch++) {
        if (ch + 1 < nch) {
            asm volatile("cp.async.wait_group 1;" ::: "memory");
        } else {
            asm volatile("cp.async.wait_group 0;" ::: "memory");
        }
        __syncthreads();
        if (ch + 2 < nch) {
            int nb = buf + 2;
            if (nb >= 3) nb -= 3;
            issue(ch + 2, nb);
        }

        uint32_t abase = sb + buf * HBUF;
        uint32_t bbase = abase + 16384;
#pragma unroll
        for (int ks = 0; ks < 4; ks++) {
            uint32_t afr[4][4];
#pragma unroll
            for (int mi = 0; mi < 4; mi++) {
                int r = wm + mi * 16 + (lane & 15);
                int cu = ks * 2 + (lane >> 4);
                uint32_t addr = abase + r * 128 + ((cu ^ (r & 7)) * 16);
                ldsm4(afr[mi], addr);
            }
            uint32_t bfr[2][4];
#pragma unroll
            for (int p = 0; p < 2; p++) {
                int r = wn + p * 16 + (lane & 7) + ((lane >> 4) * 8);
                int cu = ks * 2 + ((lane >> 3) & 1);
                uint32_t addr = bbase + r * 128 + ((cu ^ (r & 7)) * 16);
                ldsm4(bfr[p], addr);
            }
#pragma unroll
            for (int mi = 0; mi < 4; mi++)
#pragma unroll
                for (int nj = 0; nj < 4; nj++)
                    mma16816(acc[mi][nj], afr[mi],
                             bfr[nj >> 1][(nj & 1) * 2 + 0],
                             bfr[nj >> 1][(nj & 1) * 2 + 1]);
        }
        if (++buf == 3) buf = 0;
    }

#pragma unroll
    for (int mi = 0; mi < 4; mi++) {
#pragma unroll
        for (int nj = 0; nj < 4; nj++) {
            int row = bm + wm + mi * 16 + (lane >> 2);
            int col = bn + wn + nj * 8 + (lane & 3) * 2;
            float b0 = bias ? bias[col] : 0.0f;
            float b1 = bias ? bias[col + 1] : 0.0f;
            float2 v0 = make_float2(acc[mi][nj][0] + b0, acc[mi][nj][1] + b1);
            float2 v1 = make_float2(acc[mi][nj][2] + b0, acc[mi][nj][3] + b1);
            *(float2*)(C + (size_t)row * N + col) = v0;
            *(float2*)(C + (size_t)(row + 8) * N + col) = v1;
        }
    }
}

// ---------------------------------------------------------------------------
// Fully-fused 3-pass refine (unchanged from R13)
// ---------------------------------------------------------------------------
#define XFo 0
#define XSo 32768
#define HSo 65536
#define W1o 131072
#define W2o 163840
#define WZo 196608
#define Zo  212992
#define ZHo 221184
#define MLP3_SMEM 229376

__global__ __launch_bounds__(256) void mlp3_tc(
    const float* __restrict__ xb, const __half* __restrict__ W1p,
    const __half* __restrict__ W2p, const float* __restrict__ Wz,
    __half* __restrict__ Axi, float* __restrict__ pcm,
    const float* __restrict__ lam_logit) {
    extern __shared__ __align__(128) char smem[];
    const uint32_t sb = smem_u32(smem);
    float* wzsp = (float*)(smem + WZo);
    float* zsp  = (float*)(smem + Zo);
    float* zhsp = (float*)(smem + ZHo);
    const int tid = threadIdx.x, lane = tid & 31, wid = tid >> 5;
    const int t = blockIdx.y, rt = blockIdx.x;
    const int wm = (wid & 1) * 64;
    const float lam = 1.0f / (1.0f + expf(-lam_logit[0]));

    {
        const __half* w1g = W1p + (size_t)t * 16384;
        const __half* w2g = W2p + (size_t)t * 16384;
        const float* wzg = Wz + (size_t)t * 4096;
#pragma unroll
        for (int i = 0; i < 8; i++) {
            int idx = tid + 256 * i;
            asm volatile("cp.async.cg.shared.global [%0], [%1], 16;"
                         :: "r"(sb + W1o + idx * 16), "l"(w1g + idx * 8));
        }
#pragma unroll
        for (int i = 0; i < 8; i++) {
            int idx = tid + 256 * i;
            asm volatile("cp.async.cg.shared.global [%0], [%1], 16;"
                         :: "r"(sb + W2o + idx * 16), "l"(w2g + idx * 8));
        }
#pragma unroll
        for (int i = 0; i < 4; i++) {
            int idx = tid + 256 * i;
            asm volatile("cp.async.cg.shared.global [%0], [%1], 16;"
                         :: "r"(sb + WZo + idx * 16), "l"(wzg + idx * 4));
        }
        asm volatile("cp.async.commit_group;" ::: "memory");
    }

#pragma unroll
    for (int i = 0; i < 4; i++) {
        int idx = tid + 256 * i;
        int lr = idx >> 3, c = idx & 7;
        int g = rt * 128 + lr;
        const float* xp = xb + ((size_t)(g >> 2) * 32 + t * 4 + (g & 3)) * 64 + c * 8;
        float4 v0 = *(const float4*)xp;
        float4 v1 = *(const float4*)(xp + 4);
        *(float4*)(smem + XFo + lr * 256 + c * 32) = v0;
        *(float4*)(smem + XFo + lr * 256 + c * 32 + 16) = v1;
        float vv[8] = {v0.x, v0.y, v0.z, v0.w, v1.x, v1.y, v1.z, v1.w};
        uint4 Hh, Ll;
        uint32_t* hw = (uint32_t*)&Hh;
        uint32_t* lw = (uint32_t*)&Ll;
#pragma unroll
        for (int j = 0; j < 4; j++) {
            float a = vv[2 * j], b = vv[2 * j + 1];
            __half ha = __float2half_rn(a), hb = __float2half_rn(b);
            hw[j] = (uint32_t)__half_as_ushort(ha) |
                    ((uint32_t)__half_as_ushort(hb) << 16);
            lw[j] = pack_h2(a - __half2float(ha), b - __half2float(hb));
        }
        int phh = c ^ (lr & 7);
        *(uint4*)(smem + XSo + lr * 256 + phh * 16) = Hh;
        *(uint4*)(smem + XSo + lr * 256 + (8 + phh) * 16) = Ll;
    }
    asm volatile("cp.async.wait_group 0;" ::: "memory");
    __syncthreads();

    const int s_loc = tid >> 3;
    const int e0 = (tid & 7) * 8;
    const int st = (rt * 32 + s_loc) * 8 + t;
    float sq_acc = 0.0f;

#pragma unroll 1
    for (int r = 0; r < 3; r++) {
        const float lamr = (r == 0) ? 1.0f : lam;

        float zv[8];
        {
            float acc[8] = {};
#pragma unroll
            for (int c = 0; c < 4; c++) {
                const float4* xf =
                    (const float4*)(smem + XFo + (s_loc * 4 + c) * 256 + e0 * 4);
                float4 a = xf[0], b = xf[1];
                acc[0] += a.x; acc[1] += a.y; acc[2] += a.z; acc[3] += a.w;
                acc[4] += b.x; acc[5] += b.y; acc[6] += b.z; acc[7] += b.w;
            }
#pragma unroll
            for (int j = 0; j < 8; j++) {
                zv[j] = 0.25f * acc[j];
                zsp[s_loc * 64 + e0 + j] = zv[j];
            }
        }
        if (r > 0) {
#pragma unroll
            for (int j = 0; j < 8; j++) {
                float diff = zhsp[s_loc * 64 + e0 + j] - zv[j];
                sq_acc = fmaf(diff, diff, sq_acc);
            }
        }
        if (r == 2) {
            float sq = sq_acc;
            sq += __shfl_down_sync(0xffffffffu, sq, 4, 8);
            sq += __shfl_down_sync(0xffffffffu, sq, 2, 8);
            sq += __shfl_down_sync(0xffffffffu, sq, 1, 8);
            if ((tid & 7) == 0) pcm[st] = sq;
        }
        if (r < 2) {
            __syncwarp();
            const float* zr = zsp + s_loc * 64;
            float acc[8] = {};
            for (int d = 0; d < 64; d++) {
                float z = zr[d];
                const float* wr = wzsp + d * 64 + e0;
#pragma unroll
                for (int j = 0; j < 8; j++) acc[j] = fmaf(z, wr[j], acc[j]);
            }
#pragma unroll
            for (int j = 0; j < 8; j++) zhsp[s_loc * 64 + e0 + j] = acc[j];
        }

        {
            float acc1[4][8][4] = {};
            const int wn1 = (wid >> 1) * 64;
#pragma unroll
            for (int ks = 0; ks < 8; ks++) {
                uint32_t afr[4][4];
#pragma unroll
                for (int mi = 0; mi < 4; mi++) {
                    int rr = wm + mi * 16 + (lane & 15);
                    int cu = ks * 2 + (lane >> 4);
                    int ph = (cu & 8) | ((cu & 7) ^ (rr & 7));
                    ldsm4(afr[mi], sb + XSo + rr * 256 + ph * 16);
                }
                uint32_t bfr[4][4];
#pragma unroll
                for (int p = 0; p < 4; p++) {
                    int rr = wn1 + p * 16 + (lane & 7) + ((lane >> 4) * 8);
                    int cu = (ks * 2 + ((lane >> 3) & 1)) & 7;
                    int ph = cu ^ (rr & 7);
                    ldsm4(bfr[p], sb + W1o + rr * 128 + ph * 16);
                }
#pragma unroll
                for (int mi = 0; mi < 4; mi++)
#pragma unroll
                    for (int nj = 0; nj < 8; nj++)
                        mma16816(acc1[mi][nj], afr[mi],
                                 bfr[nj >> 1][(nj & 1) * 2 + 0],
                                 bfr[nj >> 1][(nj & 1) * 2 + 1]);
            }
#pragma unroll
            for (int mi = 0; mi < 4; mi++)
#pragma unroll
                for (int nj = 0; nj < 8; nj++) {
                    int r0 = wm + mi * 16 + (lane >> 2);
                    int n0 = wn1 + nj * 8 + (lane & 3) * 2;
                    float g0 = gelu_f(acc1[mi][nj][0]);
                    float g1 = gelu_f(acc1[mi][nj][1]);
                    float g2 = gelu_f(acc1[mi][nj][2]);
                    float g3 = gelu_f(acc1[mi][nj][3]);
                    uint32_t hi0 = pack_h2(g0, g1);
                    uint32_t hi1 = pack_h2(g2, g3);
                    int ch = n0 >> 3, within = (n0 & 7) * 2;
                    int ph0 = (ch & ~7) | ((ch & 7) ^ (r0 & 7));
                    int ph1 = (ch & ~7) | ((ch & 7) ^ ((r0 + 8) & 7));
                    *(uint32_t*)(smem + HSo + r0 * 512 + ph0 * 16 + within) = hi0;
                    *(uint32_t*)(smem + HSo + (r0 + 8) * 512 + ph1 * 16 + within) = hi1;
                }
        }
        __syncthreads();

        float acc2[4][2][4] = {};
        const int wn2 = (wid >> 1) * 16;
#pragma unroll
        for (int ks = 0; ks < 16; ks++) {
            uint32_t afr[4][4];
#pragma unroll
            for (int mi = 0; mi < 4; mi++) {
                int rr = wm + mi * 16 + (lane & 15);
                int cu = ks * 2 + (lane >> 4);
                int ph = (cu & ~7) | ((cu & 7) ^ (rr & 7));
                ldsm4(afr[mi], sb + HSo + rr * 512 + ph * 16);
            }
            uint32_t bfr[4];
            {
                int rr = wn2 + (lane & 7) + ((lane >> 4) * 8);
                int cu = ks * 2 + ((lane >> 3) & 1);
                int ph = (cu & ~7) | ((cu & 7) ^ (rr & 7));
                ldsm4(bfr, sb + W2o + rr * 512 + ph * 16);
            }
#pragma unroll
            for (int mi = 0; mi < 4; mi++)
#pragma unroll
                for (int nj = 0; nj < 2; nj++)
                    mma16816(acc2[mi][nj], afr[mi], bfr[nj * 2], bfr[nj * 2 + 1]);
        }

#pragma unroll
        for (int mi = 0; mi < 4; mi++)
#pragma unroll
            for (int nj = 0; nj < 2; nj++) {
                int n0 = wn2 + nj * 8 + (lane & 3) * 2;
#pragma unroll
                for (int h = 0; h < 2; h++) {
                    int lr = wm + mi * 16 + (lane >> 2) + h * 8;
                    float* xf = (float*)(smem + XFo + lr * 256 + n0 * 4);
                    float nx = xf[0] + lamr * acc2[mi][nj][h * 2 + 0];
                    float ny = xf[1] + lamr * acc2[mi][nj][h * 2 + 1];
                    __half hx = __float2half_rn(nx), hy = __float2half_rn(ny);
                    uint32_t hiw = (uint32_t)__half_as_ushort(hx) |
                                   ((uint32_t)__half_as_ushort(hy) << 16);
                    uint32_t low = pack_h2(nx - __half2float(hx),
                                           ny - __half2float(hy));
                    if (r < 2) {
                        xf[0] = nx; xf[1] = ny;
                        int ph = (n0 >> 3) ^ (lr & 7);
                        *(uint32_t*)(smem + XSo + lr * 256 + ph * 16 +
                                     (n0 & 7) * 2) = hiw;
                        *(uint32_t*)(smem + XSo + lr * 256 + (8 + ph) * 16 +
                                     (n0 & 7) * 2) = low;
                    } else {
                        int g = rt * 128 + lr;
                        size_t base = (size_t)(g >> 2) * 4096 + t * 256 +
                                      (g & 3) * 64 + n0;
                        *(uint32_t*)(Axi + base) = hiw;
                        *(uint32_t*)(Axi + base + 2048) = low;
                    }
                }
            }
        __syncthreads();
    }
}

// ---------------------------------------------------------------------------
// LayerNorm fused with fp16 conversion
// ---------------------------------------------------------------------------
__global__ void ln_kernel(const float* __restrict__ x,
                          const float* __restrict__ g,
                          const float* __restrict__ b,
                          __half* __restrict__ Ah) {
    __shared__ float red[256];
    const int s = blockIdx.x, tid = threadIdx.x;
    const float4* row = (const float4*)(x + (size_t)s * D_DIM);
    float4 v = row[tid];
    red[tid] = v.x + v.y + v.z + v.w;
    __syncthreads();
    for (int o = 128; o > 0; o >>= 1) {
        if (tid < o) red[tid] += red[tid + o];
        __syncthreads();
    }
    float mu = red[0] * (1.0f / 1024.0f);
    __syncthreads();
    float dx = v.x - mu, dy = v.y - mu, dz = v.z - mu, dw = v.w - mu;
    red[tid] = dx * dx + dy * dy + dz * dz + dw * dw;
    __syncthreads();
    for (int o = 128; o > 0; o >>= 1) {
        if (tid < o) red[tid] += red[tid + o];
        __syncthreads();
    }
    float rstd = rsqrtf(red[0] * (1.0f / 1024.0f) + 1e-5f);
    float4 gg = ((const float4*)g)[tid];
    float4 bb = ((const float4*)b)[tid];
    float ox = dx * rstd * gg.x + bb.x;
    float oy = dy * rstd * gg.y + bb.y;
    float oz = dz * rstd * gg.z + bb.z;
    float ow = dw * rstd * gg.w + bb.w;
    uint2 H;
    H.x = pack_h2(ox, oy);
    H.y = pack_h2(oz, ow);
    ((uint2*)(Ah + (size_t)s * D_DIM))[tid] = H;
}

// ---------------------------------------------------------------------------
// Deterministic aux reduction
// ---------------------------------------------------------------------------
__global__ void aux_kernel(const float* __restrict__ pcm, float* __restrict__ out) {
    __shared__ float red[256];
    const int tid = threadIdx.x;
    float s = 0.0f;
    for (int i = tid; i < S_TOT * NB; i += 256) s += pcm[i];
    red[tid] = s;
    __syncthreads();
    for (int o = 128; o > 0; o >>= 1) {
        if (tid < o) red[tid] += red[tid + o];
        __syncthreads();
    }
    if (tid == 0) out[0] = 0.1f * red[0] / 262144.0f;
}

// ---------------------------------------------------------------------------
extern "C" void kernel_launch(void* const* d_in, const int* in_sizes, int n_in,
                              void* d_out, int out_size) {
    const int*   ids  = (const int*)d_in[0];
    const float* emb  = (const float*)d_in[1];
    const float* pos  = (const float*)d_in[2];
    const float* fo_w = (const float*)d_in[3];
    const float* fo_b = (const float*)d_in[4];
    const float* W1   = (const float*)d_in[5];
    const float* W2   = (const float*)d_in[6];
    const float* Wz   = (const float*)d_in[7];
    const float* fi_w = (const float*)d_in[8];
    const float* fi_b = (const float*)d_in[9];
    const float* ln_g = (const float*)d_in[10];
    const float* ln_b = (const float*)d_in[11];
    const float* lamp = (const float*)d_in[12];
    float* out = (float*)d_out;

    float *x, *xb, *pcm;
    __half *Ah, *Bh, *Axo, *Bfo, *Axi, *Bfi, *W1p, *W2p;
    cudaGetSymbolAddress((void**)&x,    g_x);
    cudaGetSymbolAddress((void**)&xb,   g_xb);
    cudaGetSymbolAddress((void**)&pcm,  g_pcm);
    cudaGetSymbolAddress((void**)&Ah,   g_Ah);
    cudaGetSymbolAddress((void**)&Bh,   g_Bh);
    cudaGetSymbolAddress((void**)&Axo,  g_Axo);
    cudaGetSymbolAddress((void**)&Bfo,  g_Bfo);
    cudaGetSymbolAddress((void**)&Axi,  g_Axi);
    cudaGetSymbolAddress((void**)&Bfi,  g_Bfi);
    cudaGetSymbolAddress((void**)&W1p,  g_W1p);
    cudaGetSymbolAddress((void**)&W2p,  g_W2p);

    cudaFuncSetAttribute(gemm_hmma, cudaFuncAttributeMaxDynamicSharedMemorySize,
                         HSMEM);
    cudaFuncSetAttribute(mlp3_tc, cudaFuncAttributeMaxDynamicSharedMemorySize,
                         MLP3_SMEM);

    // 1. merged prep: embed+split, Bh, BfoT, BfiT, W1p, W2p — ONE launch
    prep_kernel<<<PREP_TOTAL, 256>>>(ids, emb, pos, fo_w, fi_w, W1, W2,
                                     Axo, Bh, Bfo, Bfi, W1p, W2p);

    // 2. fan_out (HMMA 2-term A, plain B with k-wrap)
    gemm_hmma<<<dim3(S_TOT / 128, T_DIM / 128), 256, HSMEM>>>(
        Axo, Bfo, fo_b, xb, 2 * D_DIM, D_DIM, T_DIM, 2 * D_DIM / 64, D_DIM - 1);

    // 3. ALL 3 refine passes in one launch; emits fan_in A-split directly
    mlp3_tc<<<dim3(128, NB), 256, MLP3_SMEM>>>(xb, W1p, W2p, Wz, Axi, pcm, lamp);

    // 4. fan_in (HMMA 2-term A, plain B with k-wrap)
    gemm_hmma<<<dim3(S_TOT / 128, D_DIM / 128), 256, HSMEM>>>(
        Axi, Bfi, fi_b, x, 2 * T_DIM, T_DIM, D_DIM, 2 * T_DIM / 64, T_DIM - 1);

    // 5. layernorm (fused fp16 output)
    ln_kernel<<<S_TOT, 256>>>(x, ln_g, ln_b, Ah);

    // 6. logits (HMMA plain fp16 A, K=1024, 128x128 tile)
    gemm_hmma<<<dim3(S_TOT / 128, V_DIM / 128), 256, HSMEM>>>(
        Ah, Bh, (const float*)0, out, 1024, 1024, V_DIM, 16, ~0);

    // 7. aux loss
    if (out_size > S_TOT * V_DIM) {
        aux_kernel<<<1, 256>>>(pcm, out + (size_t)S_TOT * V_DIM);
    }
}